// round 2
// baseline (speedup 1.0000x reference)
#include <cuda_runtime.h>
#include <cuda_bf16.h>

// ChronoRotationTransflormation: 6 inputs [B=8192, D=2048] fp32 ->
//   out[b] = ab / sqrt(aa*bb) with
//   rot_r = hr*rr - hi*ri ; rot_i = -(hi*rr + hr*ri)
//   ab = sum(rot_r*tr + rot_i*ti); aa = sum(|rot|^2); bb = sum(tr^2+ti^2)
//
// Strictly HBM-bound (402.7 MB read, 32 KB written).
// R2 design: warp-per-row. 96 LDG.128 per lane per row, unrolled x4
// (24 independent loads in flight), no CTA barriers, single warp
// butterfly reduction per row. 1024 long-lived CTAs -> fewer waves.

#define D_DIM 2048
#define D4    (D_DIM / 4)     // 512 float4 per row
#define THREADS 256
#define WARPS_PER_CTA (THREADS / 32)
#define CHUNKS (D4 / 32)      // 16 float4 per lane per array

__device__ __forceinline__ float4 ldcs4(const float4* p) {
    return __ldcs(p);
}

__global__ __launch_bounds__(THREADS, 2)
void chrono_rot_kernel(const float4* __restrict__ hr,
                       const float4* __restrict__ hi,
                       const float4* __restrict__ rr,
                       const float4* __restrict__ ri,
                       const float4* __restrict__ tr,
                       const float4* __restrict__ ti,
                       float* __restrict__ out)
{
    const int lane = threadIdx.x & 31;
    const int wid  = threadIdx.x >> 5;
    const int b    = blockIdx.x * WARPS_PER_CTA + wid;   // one row per warp

    const size_t base = (size_t)b * D4 + lane;

    float ab = 0.f, aa = 0.f, bb = 0.f;

    #pragma unroll 4
    for (int c = 0; c < CHUNKS; ++c) {
        const size_t idx = base + (size_t)c * 32;
        const float4 HR = ldcs4(hr + idx);
        const float4 HI = ldcs4(hi + idx);
        const float4 RR = ldcs4(rr + idx);
        const float4 RI = ldcs4(ri + idx);
        const float4 TR = ldcs4(tr + idx);
        const float4 TI = ldcs4(ti + idx);

        #pragma unroll
        for (int k = 0; k < 4; ++k) {
            const float hrk = (&HR.x)[k];
            const float hik = (&HI.x)[k];
            const float rrk = (&RR.x)[k];
            const float rik = (&RI.x)[k];
            const float trk = (&TR.x)[k];
            const float tik = (&TI.x)[k];

            const float rot_r = hrk * rrk - hik * rik;
            const float rot_i = -(hik * rrk + hrk * rik);

            ab = fmaf(rot_r, trk, fmaf(rot_i, tik, ab));
            aa = fmaf(rot_r, rot_r, fmaf(rot_i, rot_i, aa));
            bb = fmaf(trk, trk, fmaf(tik, tik, bb));
        }
    }

    // Warp butterfly reduction — no shared memory, no barriers.
    #pragma unroll
    for (int off = 16; off > 0; off >>= 1) {
        ab += __shfl_xor_sync(0xFFFFFFFFu, ab, off);
        aa += __shfl_xor_sync(0xFFFFFFFFu, aa, off);
        bb += __shfl_xor_sync(0xFFFFFFFFu, bb, off);
    }

    if (lane == 0) {
        out[b] = ab * rsqrtf(aa * bb);
    }
}

extern "C" void kernel_launch(void* const* d_in, const int* in_sizes, int n_in,
                              void* d_out, int out_size)
{
    const float4* hr = (const float4*)d_in[0];
    const float4* hi = (const float4*)d_in[1];
    const float4* rr = (const float4*)d_in[2];
    const float4* ri = (const float4*)d_in[3];
    const float4* tr = (const float4*)d_in[4];
    const float4* ti = (const float4*)d_in[5];
    float* out = (float*)d_out;

    const int B = in_sizes[0] / D_DIM;          // 8192
    const int grid = B / WARPS_PER_CTA;         // 1024 CTAs, one row per warp
    chrono_rot_kernel<<<grid, THREADS>>>(hr, hi, rr, ri, tr, ti, out);
}